// round 1
// baseline (speedup 1.0000x reference)
#include <cuda_runtime.h>

// NormalShader fused kernel for GB300 (sm_103a).
// N=4, H=512, W=512, K=8, V=100000, F=200000.
//
// Math exploited:
//  1) exp((z_inv - z_max)/1e-4) == 0 (fp32 underflow) unless z_inv within
//     ~30*GAMMA = 3e-3 of the max -> only the argmax sample (exp==1 exactly)
//     plus rare near-ties contribute. All gathers/sigmoids for dead samples
//     are skipped.
//  2) output = normalize(rgb), rgb = v/denom with scalar denom>0 ->
//     denom cancels; never computed.
//  3) delta = max(exp((EPS - z_max)*1e4), EPS) == EPS unless z_max < 2.4e-3
//     (essentially never) -> branch away the exp.

#define K_SAMP 8

__global__ __launch_bounds__(256)
void normal_shader_kernel(const int*   __restrict__ p2f,
                          const float* __restrict__ bary,
                          const float* __restrict__ zbuf,
                          const float* __restrict__ dists,
                          const float* __restrict__ vnorm,
                          const int*   __restrict__ faces,
                          float*       __restrict__ out,
                          int npix)
{
    const float ZFAR = 100.0f;
    const float INV_ZRANGE = 1.0f / 99.0f;
    const float INV_SIGMA = 1.0e4f;   // 1/SIGMA
    const float INV_GAMMA = 1.0e4f;   // 1/GAMMA
    const float EPS = 1.0e-10f;

    int pix = blockIdx.x * blockDim.x + threadIdx.x;
    if (pix >= npix) return;

    // ---- vectorized loads of the K=8 row (32B aligned) ----
    int4  f0 = reinterpret_cast<const int4*  >(p2f )[pix * 2 + 0];
    int4  f1 = reinterpret_cast<const int4*  >(p2f )[pix * 2 + 1];
    float4 z0 = reinterpret_cast<const float4*>(zbuf)[pix * 2 + 0];
    float4 z1 = reinterpret_cast<const float4*>(zbuf)[pix * 2 + 1];

    int   pf[K_SAMP] = {f0.x, f0.y, f0.z, f0.w, f1.x, f1.y, f1.z, f1.w};
    float zv[K_SAMP] = {z0.x, z0.y, z0.z, z0.w, z1.x, z1.y, z1.z, z1.w};

    // ---- z_inv + argmax ----
    float zinv[K_SAMP];
    float zmax_raw = 0.0f;
    int   kmax = -1;
    #pragma unroll
    for (int k = 0; k < K_SAMP; k++) {
        float zi = (pf[k] >= 0) ? (ZFAR - zv[k]) * INV_ZRANGE : 0.0f;
        zinv[k] = zi;
        if (zi > zmax_raw) { zmax_raw = zi; kmax = k; }
    }
    float zmax = fmaxf(zmax_raw, EPS);

    // ---- delta (almost always EPS) ----
    float delta = EPS;
    if (zmax < 2.4e-3f) {   // exp((EPS - zmax)*1e4) > 1e-10 only here
        delta = fmaxf(__expf((EPS - zmax) * INV_GAMMA), EPS);
    }

    float ax = 0.0f, ay = 0.0f, az = 0.0f;

    // contributor body: weight w already includes the exp factor
    auto contrib = [&](int k, float ew) {
        float d = dists[pix * K_SAMP + k];
        // sigmoid(-d/sigma) = 1 / (1 + exp(d/sigma))
        float prob = 1.0f / (1.0f + __expf(d * INV_SIGMA));
        float w = prob * ew;

        int f = pf[k];
        int v0 = faces[f * 3 + 0];
        int v1 = faces[f * 3 + 1];
        int v2 = faces[f * 3 + 2];

        int bb = (pix * K_SAMP + k) * 3;
        float b0 = bary[bb + 0];
        float b1 = bary[bb + 1];
        float b2 = bary[bb + 2];

        const float* n0 = vnorm + v0 * 3;
        const float* n1 = vnorm + v1 * 3;
        const float* n2 = vnorm + v2 * 3;

        float nx = fmaf(b0, n0[0], fmaf(b1, n1[0], b2 * n2[0]));
        float ny = fmaf(b0, n0[1], fmaf(b1, n1[1], b2 * n2[1]));
        float nz = fmaf(b0, n0[2], fmaf(b1, n1[2], b2 * n2[2]));

        ax = fmaf(w, nx, ax);
        ay = fmaf(w, ny, ay);
        az = fmaf(w, nz, az);
    };

    // ---- argmax sample: t = (zinv - zmax)/GAMMA == 0 exactly (or > -1e-6
    // when zmax was clamped to EPS) -> exp factor == 1 to within 1e-6.
    if (kmax >= 0) {
        contrib(kmax, 1.0f);
    }

    // ---- rare near-ties: exp factor meaningful only when t > -30 ----
    #pragma unroll
    for (int k = 0; k < K_SAMP; k++) {
        if (k == kmax || pf[k] < 0) continue;
        float t = (zinv[k] - zmax) * INV_GAMMA;   // <= 0
        if (t > -30.0f) {
            contrib(k, __expf(t));
        }
    }

    // ---- v = acc + delta*BG; output = (normalize(v)+1)/2 (denom cancels) ----
    float vx = ax + delta;
    float vy = ay + delta;
    float vz = az + delta;
    float n2 = fmaf(vx, vx, fmaf(vy, vy, vz * vz));
    float inv = rsqrtf(fmaxf(n2, 1e-24f));

    out[pix * 3 + 0] = fmaf(vx * inv, 0.5f, 0.5f);
    out[pix * 3 + 1] = fmaf(vy * inv, 0.5f, 0.5f);
    out[pix * 3 + 2] = fmaf(vz * inv, 0.5f, 0.5f);
}

extern "C" void kernel_launch(void* const* d_in, const int* in_sizes, int n_in,
                              void* d_out, int out_size)
{
    const int*   p2f   = (const int*  )d_in[0];  // (N,H,W,K)
    const float* bary  = (const float*)d_in[1];  // (N,H,W,K,3)
    const float* zbuf  = (const float*)d_in[2];  // (N,H,W,K)
    const float* dists = (const float*)d_in[3];  // (N,H,W,K)
    const float* vnorm = (const float*)d_in[4];  // (V,3)
    const int*   faces = (const int*  )d_in[5];  // (F,3)
    float* out = (float*)d_out;                  // (N,H,W,3)

    int npix = in_sizes[0] / K_SAMP;             // N*H*W
    int threads = 256;
    int blocks = (npix + threads - 1) / threads;
    normal_shader_kernel<<<blocks, threads>>>(p2f, bary, zbuf, dists,
                                              vnorm, faces, out, npix);
}

// round 2
// speedup vs baseline: 1.0587x; 1.0587x over previous
#include <cuda_runtime.h>

// NormalShader fused kernel, R2.
// Exploits:
//  1) exp((z_inv-z_max)/1e-4) underflows to 0 unless within 3e-3 of max ->
//     only argmax contributes except rare near-ties (~2.4% of pixels).
//  2) output = normalize(rgb): scalar denom cancels. For the single-
//     contributor case the sigmoid prob is ALSO a positive scalar factor
//     (delta=1e-10 negligible) -> fast path needs NO dists load, NO sigmoid.
//  3) all-background pixels -> constant output (1/sqrt(3)+1)/2.
//  4) smem repack -> fully coalesced float4 output stores.

#define K_SAMP 8
#define BLK 256

__global__ __launch_bounds__(BLK)
void normal_shader_kernel(const int*   __restrict__ p2f,
                          const float* __restrict__ bary,
                          const float* __restrict__ zbuf,
                          const float* __restrict__ dists,
                          const float* __restrict__ vnorm,
                          const int*   __restrict__ faces,
                          float*       __restrict__ out,
                          int npix)
{
    __shared__ float s[BLK * 3];

    const float ZFAR = 100.0f;
    const float INV_ZRANGE = 1.0f / 99.0f;
    const float INV_SIGMA = 1.0e4f;
    const float INV_GAMMA = 1.0e4f;
    const float EPS = 1.0e-10f;

    int tid = threadIdx.x;
    int pix = blockIdx.x * BLK + tid;

    float vx = 0.577350269f, vy = 0.577350269f, vz = 0.577350269f; // bg dir

    if (pix < npix) {
        // ---- vectorized loads of the K=8 row (32B aligned) ----
        int4   f0 = reinterpret_cast<const int4*  >(p2f )[pix * 2 + 0];
        int4   f1 = reinterpret_cast<const int4*  >(p2f )[pix * 2 + 1];
        float4 z0 = reinterpret_cast<const float4*>(zbuf)[pix * 2 + 0];
        float4 z1 = reinterpret_cast<const float4*>(zbuf)[pix * 2 + 1];

        int   pf[K_SAMP] = {f0.x, f0.y, f0.z, f0.w, f1.x, f1.y, f1.z, f1.w};
        float zv[K_SAMP] = {z0.x, z0.y, z0.z, z0.w, z1.x, z1.y, z1.z, z1.w};

        // ---- z_inv + argmax ----
        float zinv[K_SAMP];
        float zmax = 0.0f;
        int   kmax = -1;
        #pragma unroll
        for (int k = 0; k < K_SAMP; k++) {
            float zi = (pf[k] >= 0) ? (ZFAR - zv[k]) * INV_ZRANGE : 0.0f;
            zinv[k] = zi;
            if (zi > zmax) { zmax = zi; kmax = k; }
        }

        if (kmax >= 0) {
            // near-tie count among other valid samples
            float thresh = zmax - 3.0e-3f;
            int nties = 0;
            #pragma unroll
            for (int k = 0; k < K_SAMP; k++)
                nties += (k != kmax && pf[k] >= 0 && zinv[k] > thresh) ? 1 : 0;

            if (nties == 0 && zmax >= 2.4e-3f) {
                // ======== FAST PATH: single contributor ========
                // output = normalize(prob * n + 1e-10*BG) ~= normalize(n);
                // prob>0 scalar -> cancels. No dists load, no MUFU exp.
                int f  = pf[kmax];
                int v0 = faces[f * 3 + 0];
                int v1 = faces[f * 3 + 1];
                int v2 = faces[f * 3 + 2];

                int bb = (pix * K_SAMP + kmax) * 3;
                float b0 = bary[bb + 0];
                float b1 = bary[bb + 1];
                float b2 = bary[bb + 2];

                const float* n0 = vnorm + v0 * 3;
                const float* n1 = vnorm + v1 * 3;
                const float* n2 = vnorm + v2 * 3;

                vx = fmaf(b0, n0[0], fmaf(b1, n1[0], b2 * n2[0]));
                vy = fmaf(b0, n0[1], fmaf(b1, n1[1], b2 * n2[1]));
                vz = fmaf(b0, n0[2], fmaf(b1, n1[2], b2 * n2[2]));
            } else {
                // ======== SLOW PATH: near-ties / tiny zmax ========
                float zm = fmaxf(zmax, EPS);
                float delta = EPS;
                if (zmax < 2.4e-3f)
                    delta = fmaxf(__expf((EPS - zm) * INV_GAMMA), EPS);

                float ax = 0.0f, ay = 0.0f, az = 0.0f;
                #pragma unroll
                for (int k = 0; k < K_SAMP; k++) {
                    if (pf[k] < 0) continue;
                    float t = (zinv[k] - zm) * INV_GAMMA;   // <= ~0
                    if (t <= -30.0f) continue;
                    float ew = __expf(t);
                    float d  = dists[pix * K_SAMP + k];
                    float prob = 1.0f / (1.0f + __expf(d * INV_SIGMA));
                    float w = prob * ew;

                    int f  = pf[k];
                    int v0 = faces[f * 3 + 0];
                    int v1 = faces[f * 3 + 1];
                    int v2 = faces[f * 3 + 2];

                    int bb = (pix * K_SAMP + k) * 3;
                    float b0 = bary[bb + 0];
                    float b1 = bary[bb + 1];
                    float b2 = bary[bb + 2];

                    const float* n0 = vnorm + v0 * 3;
                    const float* n1 = vnorm + v1 * 3;
                    const float* n2 = vnorm + v2 * 3;

                    float nx = fmaf(b0, n0[0], fmaf(b1, n1[0], b2 * n2[0]));
                    float ny = fmaf(b0, n0[1], fmaf(b1, n1[1], b2 * n2[1]));
                    float nz = fmaf(b0, n0[2], fmaf(b1, n1[2], b2 * n2[2]));

                    ax = fmaf(w, nx, ax);
                    ay = fmaf(w, ny, ay);
                    az = fmaf(w, nz, az);
                }
                vx = ax + delta;
                vy = ay + delta;
                vz = az + delta;
            }
        }
        // else: all background -> constant bg direction already set
    }

    // ---- normalize + map to [0,1] ----
    float n2  = fmaf(vx, vx, fmaf(vy, vy, vz * vz));
    float inv = rsqrtf(fmaxf(n2, 1e-24f));
    s[tid * 3 + 0] = fmaf(vx * inv, 0.5f, 0.5f);
    s[tid * 3 + 1] = fmaf(vy * inv, 0.5f, 0.5f);
    s[tid * 3 + 2] = fmaf(vz * inv, 0.5f, 0.5f);

    __syncthreads();

    // ---- coalesced float4 stores: 256 pixels * 3 floats = 192 float4 ----
    long fbase = (long)blockIdx.x * (BLK * 3);
    long ftotal = (long)npix * 3;
    if (fbase + BLK * 3 <= ftotal) {
        if (tid < (BLK * 3) / 4) {
            reinterpret_cast<float4*>(out)[fbase / 4 + tid] =
                reinterpret_cast<const float4*>(s)[tid];
        }
    } else {
        // tail block: scalar stores
        for (int i = tid; i < BLK * 3; i += BLK) {
            long fi = fbase + i;
            if (fi < ftotal) out[fi] = s[i];
        }
    }
}

extern "C" void kernel_launch(void* const* d_in, const int* in_sizes, int n_in,
                              void* d_out, int out_size)
{
    const int*   p2f   = (const int*  )d_in[0];
    const float* bary  = (const float*)d_in[1];
    const float* zbuf  = (const float*)d_in[2];
    const float* dists = (const float*)d_in[3];
    const float* vnorm = (const float*)d_in[4];
    const int*   faces = (const int*  )d_in[5];
    float* out = (float*)d_out;

    int npix = in_sizes[0] / K_SAMP;
    int blocks = (npix + BLK - 1) / BLK;
    normal_shader_kernel<<<blocks, BLK>>>(p2f, bary, zbuf, dists,
                                          vnorm, faces, out, npix);
}

// round 3
// speedup vs baseline: 1.1103x; 1.0487x over previous
#include <cuda_runtime.h>

// NormalShader fused kernel, R3: 2 pixels/thread for gather-chain MLP,
// branch-free kmax gather, rare slow path for near-ties.

#define K_SAMP 8
#define BLK 256
#define PPT 2

__global__ __launch_bounds__(BLK)
void normal_shader_kernel(const int*   __restrict__ p2f,
                          const float* __restrict__ bary,
                          const float* __restrict__ zbuf,
                          const float* __restrict__ dists,
                          const float* __restrict__ vnorm,
                          const int*   __restrict__ faces,
                          float*       __restrict__ out,
                          int npix)
{
    __shared__ float s[BLK * PPT * 3];

    const float ZFAR = 100.0f;
    const float INV_ZRANGE = 1.0f / 99.0f;
    const float INV_SIGMA = 1.0e4f;
    const float INV_GAMMA = 1.0e4f;
    const float EPS = 1.0e-10f;
    const float BGDIR = 0.577350269f;

    int tid  = threadIdx.x;
    int base = blockIdx.x * (BLK * PPT);

    #pragma unroll
    for (int p = 0; p < PPT; p++) {
        int pix  = base + p * BLK + tid;
        bool inb = pix < npix;
        int pixc = inb ? pix : 0;

        // ---- vectorized row loads (32B aligned) ----
        int4   f0 = reinterpret_cast<const int4*  >(p2f )[pixc * 2 + 0];
        int4   f1 = reinterpret_cast<const int4*  >(p2f )[pixc * 2 + 1];
        float4 z0 = reinterpret_cast<const float4*>(zbuf)[pixc * 2 + 0];
        float4 z1 = reinterpret_cast<const float4*>(zbuf)[pixc * 2 + 1];

        int   pf[K_SAMP] = {f0.x, f0.y, f0.z, f0.w, f1.x, f1.y, f1.z, f1.w};
        float zv[K_SAMP] = {z0.x, z0.y, z0.z, z0.w, z1.x, z1.y, z1.z, z1.w};

        // ---- z_inv + argmax (track fsel: no dynamic register indexing) ----
        float zinv[K_SAMP];
        float zmax = 0.0f;
        int   ksel = -1;
        int   fsel = 0;
        #pragma unroll
        for (int k = 0; k < K_SAMP; k++) {
            float zi = (pf[k] >= 0) ? (ZFAR - zv[k]) * INV_ZRANGE : 0.0f;
            zinv[k] = zi;
            if (zi > zmax) { zmax = zi; ksel = k; fsel = pf[k]; }
        }
        bool valid = (ksel >= 0);

        // ---- unconditional (predicated-safe) gather for the argmax sample:
        // keeps the 3-deep load chain issuing without a divergent branch. ----
        int f  = valid ? fsel : 0;
        int v0 = faces[f * 3 + 0];
        int v1 = faces[f * 3 + 1];
        int v2 = faces[f * 3 + 2];

        int bb = (pixc * K_SAMP + (valid ? ksel : 0)) * 3;
        float b0 = bary[bb + 0];
        float b1 = bary[bb + 1];
        float b2 = bary[bb + 2];

        const float* n0 = vnorm + v0 * 3;
        const float* n1 = vnorm + v1 * 3;
        const float* n2 = vnorm + v2 * 3;

        float nx = fmaf(b0, n0[0], fmaf(b1, n1[0], b2 * n2[0]));
        float ny = fmaf(b0, n0[1], fmaf(b1, n1[1], b2 * n2[1]));
        float nz = fmaf(b0, n0[2], fmaf(b1, n1[2], b2 * n2[2]));

        // ---- near-tie detection (exp(t) >= e^-15 matters vs 1e-3 tol) ----
        float thresh = zmax - 1.5e-3f;
        bool ties = false;
        #pragma unroll
        for (int k = 0; k < K_SAMP; k++)
            ties |= (k != ksel && pf[k] >= 0 && zinv[k] > thresh);

        float vx, vy, vz;
        if (!valid) {
            vx = BGDIR; vy = BGDIR; vz = BGDIR;      // all background
        } else if (!ties && zmax >= 2.4e-3f) {
            // FAST: single contributor; prob & denom cancel in normalize
            vx = nx; vy = ny; vz = nz;
        } else {
            // SLOW (rare): full weights for all samples within 3e-3 of max
            float zm = fmaxf(zmax, EPS);
            float delta = EPS;
            if (zmax < 2.4e-3f)
                delta = fmaxf(__expf((EPS - zm) * INV_GAMMA), EPS);

            float4 d0 = reinterpret_cast<const float4*>(dists)[pixc * 2 + 0];
            float4 d1 = reinterpret_cast<const float4*>(dists)[pixc * 2 + 1];
            float dv[K_SAMP] = {d0.x, d0.y, d0.z, d0.w, d1.x, d1.y, d1.z, d1.w};

            float ax = 0.0f, ay = 0.0f, az = 0.0f;
            float lim = zm - 3.0e-3f;
            #pragma unroll
            for (int k = 0; k < K_SAMP; k++) {
                if (pf[k] < 0 || zinv[k] <= lim) continue;
                float ew = __expf((zinv[k] - zm) * INV_GAMMA);
                float prob = 1.0f / (1.0f + __expf(dv[k] * INV_SIGMA));
                float w = prob * ew;

                int ff  = pf[k];
                int u0 = faces[ff * 3 + 0];
                int u1 = faces[ff * 3 + 1];
                int u2 = faces[ff * 3 + 2];

                int bk = (pixc * K_SAMP + k) * 3;
                float c0 = bary[bk + 0];
                float c1 = bary[bk + 1];
                float c2 = bary[bk + 2];

                const float* m0 = vnorm + u0 * 3;
                const float* m1 = vnorm + u1 * 3;
                const float* m2 = vnorm + u2 * 3;

                float gx = fmaf(c0, m0[0], fmaf(c1, m1[0], c2 * m2[0]));
                float gy = fmaf(c0, m0[1], fmaf(c1, m1[1], c2 * m2[1]));
                float gz = fmaf(c0, m0[2], fmaf(c1, m1[2], c2 * m2[2]));

                ax = fmaf(w, gx, ax);
                ay = fmaf(w, gy, ay);
                az = fmaf(w, gz, az);
            }
            vx = ax + delta;
            vy = ay + delta;
            vz = az + delta;
        }

        // ---- normalize + map to [0,1], stage in smem ----
        float nn  = fmaf(vx, vx, fmaf(vy, vy, vz * vz));
        float inv = rsqrtf(fmaxf(nn, 1e-24f));
        int si = (p * BLK + tid) * 3;
        s[si + 0] = fmaf(vx * inv, 0.5f, 0.5f);
        s[si + 1] = fmaf(vy * inv, 0.5f, 0.5f);
        s[si + 2] = fmaf(vz * inv, 0.5f, 0.5f);
    }

    __syncthreads();

    // ---- coalesced float4 stores: BLK*PPT*3 floats = 384 float4 ----
    const int NF  = BLK * PPT * 3;       // 1536 floats
    const int NV4 = NF / 4;              // 384
    long fbase  = (long)blockIdx.x * NF;
    long ftotal = (long)npix * 3;
    if (fbase + NF <= ftotal) {
        #pragma unroll
        for (int i = tid; i < NV4; i += BLK) {
            reinterpret_cast<float4*>(out)[fbase / 4 + i] =
                reinterpret_cast<const float4*>(s)[i];
        }
    } else {
        for (int i = tid; i < NF; i += BLK) {
            long fi = fbase + i;
            if (fi < ftotal) out[fi] = s[i];
        }
    }
}

extern "C" void kernel_launch(void* const* d_in, const int* in_sizes, int n_in,
                              void* d_out, int out_size)
{
    const int*   p2f   = (const int*  )d_in[0];
    const float* bary  = (const float*)d_in[1];
    const float* zbuf  = (const float*)d_in[2];
    const float* dists = (const float*)d_in[3];
    const float* vnorm = (const float*)d_in[4];
    const int*   faces = (const int*  )d_in[5];
    float* out = (float*)d_out;

    int npix = in_sizes[0] / K_SAMP;
    int blocks = (npix + BLK * PPT - 1) / (BLK * PPT);
    normal_shader_kernel<<<blocks, BLK>>>(p2f, bary, zbuf, dists,
                                          vnorm, faces, out, npix);
}

// round 4
// speedup vs baseline: 1.2163x; 1.0955x over previous
#include <cuda_runtime.h>

// NormalShader fused, R4: precompute packed per-face vertex-normal table
// (float4 x3 per face) -> main kernel gather chain depth 2, 3 vector LDGs.

#define K_SAMP 8
#define BLK 256
#define PPT 2
#define F_MAX 200000

__device__ float4 g_packed[F_MAX * 3];   // 9.6 MB, L2-resident

__global__ __launch_bounds__(256)
void pack_faces_kernel(const int*   __restrict__ faces,
                       const float* __restrict__ vnorm,
                       int F)
{
    int f = blockIdx.x * blockDim.x + threadIdx.x;
    if (f >= F) return;
    int v0 = faces[f * 3 + 0];
    int v1 = faces[f * 3 + 1];
    int v2 = faces[f * 3 + 2];
    const float* n0 = vnorm + v0 * 3;
    const float* n1 = vnorm + v1 * 3;
    const float* n2 = vnorm + v2 * 3;
    g_packed[f * 3 + 0] = make_float4(n0[0], n0[1], n0[2], 0.0f);
    g_packed[f * 3 + 1] = make_float4(n1[0], n1[1], n1[2], 0.0f);
    g_packed[f * 3 + 2] = make_float4(n2[0], n2[1], n2[2], 0.0f);
}

__global__ __launch_bounds__(BLK)
void normal_shader_kernel(const int*   __restrict__ p2f,
                          const float* __restrict__ bary,
                          const float* __restrict__ zbuf,
                          const float* __restrict__ dists,
                          float*       __restrict__ out,
                          int npix)
{
    __shared__ float s[BLK * PPT * 3];

    const float ZFAR = 100.0f;
    const float INV_ZRANGE = 1.0f / 99.0f;
    const float INV_SIGMA = 1.0e4f;
    const float INV_GAMMA = 1.0e4f;
    const float EPS = 1.0e-10f;
    const float BGDIR = 0.577350269f;

    int tid  = threadIdx.x;
    int base = blockIdx.x * (BLK * PPT);

    #pragma unroll
    for (int p = 0; p < PPT; p++) {
        int pix  = base + p * BLK + tid;
        bool inb = pix < npix;
        int pixc = inb ? pix : 0;

        // ---- vectorized row loads (32B aligned) ----
        int4   f0 = reinterpret_cast<const int4*  >(p2f )[pixc * 2 + 0];
        int4   f1 = reinterpret_cast<const int4*  >(p2f )[pixc * 2 + 1];
        float4 z0 = reinterpret_cast<const float4*>(zbuf)[pixc * 2 + 0];
        float4 z1 = reinterpret_cast<const float4*>(zbuf)[pixc * 2 + 1];

        int   pf[K_SAMP] = {f0.x, f0.y, f0.z, f0.w, f1.x, f1.y, f1.z, f1.w};
        float zv[K_SAMP] = {z0.x, z0.y, z0.z, z0.w, z1.x, z1.y, z1.z, z1.w};

        // ---- z_inv + argmax (track face id: no dynamic reg indexing) ----
        float zinv[K_SAMP];
        float zmax = 0.0f;
        int   ksel = -1;
        int   fsel = 0;
        #pragma unroll
        for (int k = 0; k < K_SAMP; k++) {
            float zi = (pf[k] >= 0) ? (ZFAR - zv[k]) * INV_ZRANGE : 0.0f;
            zinv[k] = zi;
            if (zi > zmax) { zmax = zi; ksel = k; fsel = pf[k]; }
        }
        bool valid = (ksel >= 0);

        // ---- unconditional gather for argmax sample: 3 x LDG.128 ----
        int f  = valid ? fsel : 0;
        float4 q0 = g_packed[f * 3 + 0];
        float4 q1 = g_packed[f * 3 + 1];
        float4 q2 = g_packed[f * 3 + 2];

        int bb = (pixc * K_SAMP + (valid ? ksel : 0)) * 3;
        float b0 = bary[bb + 0];
        float b1 = bary[bb + 1];
        float b2 = bary[bb + 2];

        float nx = fmaf(b0, q0.x, fmaf(b1, q1.x, b2 * q2.x));
        float ny = fmaf(b0, q0.y, fmaf(b1, q1.y, b2 * q2.y));
        float nz = fmaf(b0, q0.z, fmaf(b1, q1.z, b2 * q2.z));

        // ---- near-tie detection ----
        float thresh = zmax - 1.5e-3f;
        bool ties = false;
        #pragma unroll
        for (int k = 0; k < K_SAMP; k++)
            ties |= (k != ksel && pf[k] >= 0 && zinv[k] > thresh);

        float vx, vy, vz;
        if (!valid) {
            vx = BGDIR; vy = BGDIR; vz = BGDIR;      // all background
        } else if (!ties && zmax >= 2.4e-3f) {
            // FAST: single contributor; prob & denom cancel in normalize
            vx = nx; vy = ny; vz = nz;
        } else {
            // SLOW (rare): full weights for samples within 3e-3 of max
            float zm = fmaxf(zmax, EPS);
            float delta = EPS;
            if (zmax < 2.4e-3f)
                delta = fmaxf(__expf((EPS - zm) * INV_GAMMA), EPS);

            float4 d0 = reinterpret_cast<const float4*>(dists)[pixc * 2 + 0];
            float4 d1 = reinterpret_cast<const float4*>(dists)[pixc * 2 + 1];
            float dv[K_SAMP] = {d0.x, d0.y, d0.z, d0.w, d1.x, d1.y, d1.z, d1.w};

            float ax = 0.0f, ay = 0.0f, az = 0.0f;
            float lim = zm - 3.0e-3f;
            #pragma unroll
            for (int k = 0; k < K_SAMP; k++) {
                if (pf[k] < 0 || zinv[k] <= lim) continue;
                float ew = __expf((zinv[k] - zm) * INV_GAMMA);
                float prob = 1.0f / (1.0f + __expf(dv[k] * INV_SIGMA));
                float w = prob * ew;

                int ff = pf[k];
                float4 m0 = g_packed[ff * 3 + 0];
                float4 m1 = g_packed[ff * 3 + 1];
                float4 m2 = g_packed[ff * 3 + 2];

                int bk = (pixc * K_SAMP + k) * 3;
                float c0 = bary[bk + 0];
                float c1 = bary[bk + 1];
                float c2 = bary[bk + 2];

                float gx = fmaf(c0, m0.x, fmaf(c1, m1.x, c2 * m2.x));
                float gy = fmaf(c0, m0.y, fmaf(c1, m1.y, c2 * m2.y));
                float gz = fmaf(c0, m0.z, fmaf(c1, m1.z, c2 * m2.z));

                ax = fmaf(w, gx, ax);
                ay = fmaf(w, gy, ay);
                az = fmaf(w, gz, az);
            }
            vx = ax + delta;
            vy = ay + delta;
            vz = az + delta;
        }

        // ---- normalize + map to [0,1], stage in smem ----
        float nn  = fmaf(vx, vx, fmaf(vy, vy, vz * vz));
        float inv = rsqrtf(fmaxf(nn, 1e-24f));
        int si = (p * BLK + tid) * 3;
        s[si + 0] = fmaf(vx * inv, 0.5f, 0.5f);
        s[si + 1] = fmaf(vy * inv, 0.5f, 0.5f);
        s[si + 2] = fmaf(vz * inv, 0.5f, 0.5f);
    }

    __syncthreads();

    // ---- coalesced float4 stores ----
    const int NF  = BLK * PPT * 3;       // 1536 floats
    const int NV4 = NF / 4;              // 384
    long fbase  = (long)blockIdx.x * NF;
    long ftotal = (long)npix * 3;
    if (fbase + NF <= ftotal) {
        #pragma unroll
        for (int i = tid; i < NV4; i += BLK) {
            reinterpret_cast<float4*>(out)[fbase / 4 + i] =
                reinterpret_cast<const float4*>(s)[i];
        }
    } else {
        for (int i = tid; i < NF; i += BLK) {
            long fi = fbase + i;
            if (fi < ftotal) out[fi] = s[i];
        }
    }
}

extern "C" void kernel_launch(void* const* d_in, const int* in_sizes, int n_in,
                              void* d_out, int out_size)
{
    const int*   p2f   = (const int*  )d_in[0];
    const float* bary  = (const float*)d_in[1];
    const float* zbuf  = (const float*)d_in[2];
    const float* dists = (const float*)d_in[3];
    const float* vnorm = (const float*)d_in[4];
    const int*   faces = (const int*  )d_in[5];
    float* out = (float*)d_out;

    int F = in_sizes[5] / 3;
    if (F > F_MAX) F = F_MAX;
    int npix = in_sizes[0] / K_SAMP;

    pack_faces_kernel<<<(F + 255) / 256, 256>>>(faces, vnorm, F);

    int blocks = (npix + BLK * PPT - 1) / (BLK * PPT);
    normal_shader_kernel<<<blocks, BLK>>>(p2f, bary, zbuf, dists, out, npix);
}

// round 5
// speedup vs baseline: 1.2578x; 1.0341x over previous
#include <cuda_runtime.h>

// NormalShader fused, R5: faster pack (3 threads/face), main kernel with
// register cap for higher occupancy.

#define K_SAMP 8
#define BLK 256
#define PPT 2
#define F_MAX 200000

__device__ float4 g_packed[F_MAX * 3];   // 9.6 MB, L2-resident

// One thread per (face, vertex-slot): coalesced idx load, 3 hot vnorm loads,
// coalesced STG.128.
__global__ __launch_bounds__(256)
void pack_faces_kernel(const int*   __restrict__ faces,
                       const float* __restrict__ vnorm,
                       int total)                  // total = F*3
{
    int j = blockIdx.x * blockDim.x + threadIdx.x;
    if (j >= total) return;
    int v = faces[j];
    const float* n = vnorm + v * 3;
    g_packed[j] = make_float4(n[0], n[1], n[2], 0.0f);
}

__global__ __launch_bounds__(BLK, 5)
void normal_shader_kernel(const int*   __restrict__ p2f,
                          const float* __restrict__ bary,
                          const float* __restrict__ zbuf,
                          const float* __restrict__ dists,
                          float*       __restrict__ out,
                          int npix)
{
    __shared__ float s[BLK * PPT * 3];

    const float ZFAR = 100.0f;
    const float INV_ZRANGE = 1.0f / 99.0f;
    const float INV_SIGMA = 1.0e4f;
    const float INV_GAMMA = 1.0e4f;
    const float EPS = 1.0e-10f;
    const float BGDIR = 0.577350269f;

    int tid  = threadIdx.x;
    int base = blockIdx.x * (BLK * PPT);

    #pragma unroll
    for (int p = 0; p < PPT; p++) {
        int pix  = base + p * BLK + tid;
        bool inb = pix < npix;
        int pixc = inb ? pix : 0;

        // ---- vectorized row loads (32B aligned) ----
        int4   f0 = reinterpret_cast<const int4*  >(p2f )[pixc * 2 + 0];
        int4   f1 = reinterpret_cast<const int4*  >(p2f )[pixc * 2 + 1];
        float4 z0 = reinterpret_cast<const float4*>(zbuf)[pixc * 2 + 0];
        float4 z1 = reinterpret_cast<const float4*>(zbuf)[pixc * 2 + 1];

        int   pf[K_SAMP] = {f0.x, f0.y, f0.z, f0.w, f1.x, f1.y, f1.z, f1.w};
        float zv[K_SAMP] = {z0.x, z0.y, z0.z, z0.w, z1.x, z1.y, z1.z, z1.w};

        // ---- z_inv + argmax (track face id: no dynamic reg indexing) ----
        float zinv[K_SAMP];
        float zmax = 0.0f;
        int   ksel = -1;
        int   fsel = 0;
        #pragma unroll
        for (int k = 0; k < K_SAMP; k++) {
            float zi = (pf[k] >= 0) ? (ZFAR - zv[k]) * INV_ZRANGE : 0.0f;
            zinv[k] = zi;
            if (zi > zmax) { zmax = zi; ksel = k; fsel = pf[k]; }
        }
        bool valid = (ksel >= 0);

        // ---- unconditional gather for argmax sample: 3 x LDG.128 ----
        int f  = valid ? fsel : 0;
        float4 q0 = g_packed[f * 3 + 0];
        float4 q1 = g_packed[f * 3 + 1];
        float4 q2 = g_packed[f * 3 + 2];

        int bb = (pixc * K_SAMP + (valid ? ksel : 0)) * 3;
        float b0 = bary[bb + 0];
        float b1 = bary[bb + 1];
        float b2 = bary[bb + 2];

        float nx = fmaf(b0, q0.x, fmaf(b1, q1.x, b2 * q2.x));
        float ny = fmaf(b0, q0.y, fmaf(b1, q1.y, b2 * q2.y));
        float nz = fmaf(b0, q0.z, fmaf(b1, q1.z, b2 * q2.z));

        // ---- near-tie detection ----
        float thresh = zmax - 1.5e-3f;
        bool ties = false;
        #pragma unroll
        for (int k = 0; k < K_SAMP; k++)
            ties |= (k != ksel && pf[k] >= 0 && zinv[k] > thresh);

        float vx, vy, vz;
        if (!valid) {
            vx = BGDIR; vy = BGDIR; vz = BGDIR;      // all background
        } else if (!ties && zmax >= 2.4e-3f) {
            // FAST: single contributor; prob & denom cancel in normalize
            vx = nx; vy = ny; vz = nz;
        } else {
            // SLOW (rare): full weights for samples within 3e-3 of max
            float zm = fmaxf(zmax, EPS);
            float delta = EPS;
            if (zmax < 2.4e-3f)
                delta = fmaxf(__expf((EPS - zm) * INV_GAMMA), EPS);

            float4 d0 = reinterpret_cast<const float4*>(dists)[pixc * 2 + 0];
            float4 d1 = reinterpret_cast<const float4*>(dists)[pixc * 2 + 1];
            float dv[K_SAMP] = {d0.x, d0.y, d0.z, d0.w, d1.x, d1.y, d1.z, d1.w};

            float ax = 0.0f, ay = 0.0f, az = 0.0f;
            float lim = zm - 3.0e-3f;
            #pragma unroll
            for (int k = 0; k < K_SAMP; k++) {
                if (pf[k] < 0 || zinv[k] <= lim) continue;
                float ew = __expf((zinv[k] - zm) * INV_GAMMA);
                float prob = 1.0f / (1.0f + __expf(dv[k] * INV_SIGMA));
                float w = prob * ew;

                int ff = pf[k];
                float4 m0 = g_packed[ff * 3 + 0];
                float4 m1 = g_packed[ff * 3 + 1];
                float4 m2 = g_packed[ff * 3 + 2];

                int bk = (pixc * K_SAMP + k) * 3;
                float c0 = bary[bk + 0];
                float c1 = bary[bk + 1];
                float c2 = bary[bk + 2];

                float gx = fmaf(c0, m0.x, fmaf(c1, m1.x, c2 * m2.x));
                float gy = fmaf(c0, m0.y, fmaf(c1, m1.y, c2 * m2.y));
                float gz = fmaf(c0, m0.z, fmaf(c1, m1.z, c2 * m2.z));

                ax = fmaf(w, gx, ax);
                ay = fmaf(w, gy, ay);
                az = fmaf(w, gz, az);
            }
            vx = ax + delta;
            vy = ay + delta;
            vz = az + delta;
        }

        // ---- normalize + map to [0,1], stage in smem ----
        float nn  = fmaf(vx, vx, fmaf(vy, vy, vz * vz));
        float inv = rsqrtf(fmaxf(nn, 1e-24f));
        int si = (p * BLK + tid) * 3;
        s[si + 0] = fmaf(vx * inv, 0.5f, 0.5f);
        s[si + 1] = fmaf(vy * inv, 0.5f, 0.5f);
        s[si + 2] = fmaf(vz * inv, 0.5f, 0.5f);
    }

    __syncthreads();

    // ---- coalesced float4 stores ----
    const int NF  = BLK * PPT * 3;       // 1536 floats
    const int NV4 = NF / 4;              // 384
    long fbase  = (long)blockIdx.x * NF;
    long ftotal = (long)npix * 3;
    if (fbase + NF <= ftotal) {
        #pragma unroll
        for (int i = tid; i < NV4; i += BLK) {
            reinterpret_cast<float4*>(out)[fbase / 4 + i] =
                reinterpret_cast<const float4*>(s)[i];
        }
    } else {
        for (int i = tid; i < NF; i += BLK) {
            long fi = fbase + i;
            if (fi < ftotal) out[fi] = s[i];
        }
    }
}

extern "C" void kernel_launch(void* const* d_in, const int* in_sizes, int n_in,
                              void* d_out, int out_size)
{
    const int*   p2f   = (const int*  )d_in[0];
    const float* bary  = (const float*)d_in[1];
    const float* zbuf  = (const float*)d_in[2];
    const float* dists = (const float*)d_in[3];
    const float* vnorm = (const float*)d_in[4];
    const int*   faces = (const int*  )d_in[5];
    float* out = (float*)d_out;

    int total = in_sizes[5];                 // F*3
    if (total > F_MAX * 3) total = F_MAX * 3;
    int npix = in_sizes[0] / K_SAMP;

    pack_faces_kernel<<<(total + 255) / 256, 256>>>(faces, vnorm, total);

    int blocks = (npix + BLK * PPT - 1) / (BLK * PPT);
    normal_shader_kernel<<<blocks, BLK>>>(p2f, bary, zbuf, dists, out, npix);
}